// round 9
// baseline (speedup 1.0000x reference)
#include <cuda_runtime.h>
#include <cuda_bf16.h>
#include <math.h>

#define BB 4
#define C 64
#define C2 128
#define H 128
#define W 128
#define HW (H*W)
#define FIELD_N (BB*C*HW)
#define TILE_H 8
#define TILE_W 16
#define NT 256
#define NBLK 512
#define MAX_STEPS 50
#define DT_C 0.1f
#define THRESH_C 0.01

// ---- smem byte offsets ----
#define SM_SF   0          // 64*180*4 = 46080 fp32 halo
#define SM_W1Q  46080      // 32768 (128 rows x 16 uint4 entries)
#define SM_W2Q  78848      // 32768 (64 rows x 32 uint4 entries)
#define SM_B1   111616     // 512
#define SM_B2   112128     // 256  (prescaled)
#define SM_DW   112640     // 2304 (prescaled)
#define SM_RED  114944     // 32
#define SMEM_BYTES 114976

typedef unsigned u32;
typedef unsigned short u16;

__device__ __forceinline__ u32 pack_bf16x2(float lo, float hi) {
    __nv_bfloat162 t = __floats2bfloat162_rn(lo, hi);
    return *reinterpret_cast<u32*>(&t);
}

__device__ __forceinline__ void mma_bf16(float* d, const u32* a, u32 b0, u32 b1) {
    asm volatile(
        "mma.sync.aligned.m16n8k16.row.col.f32.bf16.bf16.f32 "
        "{%0,%1,%2,%3}, {%4,%5,%6,%7}, {%8,%9}, {%0,%1,%2,%3};"
        : "+f"(d[0]), "+f"(d[1]), "+f"(d[2]), "+f"(d[3])
        : "r"(a[0]), "r"(a[1]), "r"(a[2]), "r"(a[3]), "r"(b0), "r"(b1));
}

// gelu(x) with A&S 7.1.26 erf approximation, |erf err| <= 1.5e-7 abs
__device__ __forceinline__ float gelu_f(float x) {
    float ax = fabsf(x) * 0.70710678118654752f;
    float t = __fdividef(1.0f, fmaf(0.3275911f, ax, 1.0f));
    float poly = t * fmaf(t, fmaf(t, fmaf(t, fmaf(t, 1.061405429f, -1.453152027f),
                                          1.421413741f), -0.284496736f), 0.254829592f);
    float e = __expf(-ax * ax);
    float er = fmaf(-poly, e, 1.0f);
    er = copysignf(er, x);
    return 0.5f * x * (1.0f + er);
}

__device__ float g_buf0[FIELD_N];
__device__ float g_buf1[FIELD_N];
__device__ int      g_done;
__device__ int      g_steps;
__device__ int      g_cur;
__device__ double   g_sum;
__device__ unsigned g_count;
// combined uint4 weight entries {bh0, bh1, bl0, bl1}, phase-swizzled
__device__ __align__(16) u32 g_w1q[8192];
__device__ __align__(16) u32 g_w2q[8192];
__device__ float g_dws[C * 9];   // DT*dc*dw
__device__ float g_b2s[C];       // DT*(dc*db + b2)

__global__ void afe_init_kernel(const float* __restrict__ field) {
    int tid = blockIdx.x * blockDim.x + threadIdx.x;
    if (tid == 0) { g_done = 0; g_steps = 0; g_cur = 0; g_sum = 0.0; g_count = 0u; }
    int stride = gridDim.x * blockDim.x;
    for (int i = tid; i < FIELD_N; i += stride) g_buf0[i] = field[i];
}

__global__ void afe_prep_weights(const float* __restrict__ w1, const float* __restrict__ w2,
                                 const float* __restrict__ dw, const float* __restrict__ db,
                                 const float* __restrict__ b2, const float* __restrict__ dcoeff) {
    int tid = blockIdx.x * blockDim.x + threadIdx.x;
    int stride = gridDim.x * blockDim.x;
    float dc = dcoeff[0];
    // W1 [j=128][word w=0..31], word w covers c = 2w, 2w+1; w = 8kc + t4 + 4q
    for (int i = tid; i < C2 * 32; i += stride) {
        int j = i >> 5, w = i & 31;
        int kc = w >> 3, rem = w & 7;
        int q = rem >> 2, t4 = rem & 3;
        int c = 2 * w;
        float v0 = w1[j * C + c], v1 = w1[j * C + c + 1];
        __nv_bfloat16 h0 = __float2bfloat16_rn(v0), h1 = __float2bfloat16_rn(v1);
        float l0 = v0 - __bfloat162float(h0), l1 = v1 - __bfloat162float(h1);
        int e_log = kc * 4 + t4;
        int e_phys = e_log ^ ((j & 1) << 2);
        int idx = j * 64 + e_phys * 4 + q;
        g_w1q[idx]     = pack_bf16x2(__bfloat162float(h0), __bfloat162float(h1));
        g_w1q[idx + 2] = pack_bf16x2(l0, l1);
    }
    // W2 [c=64][word w=0..63], word w covers j = 2w, 2w+1; w = 8kc + t4 + 4q
    for (int i = tid; i < C * 64; i += stride) {
        int cc = i >> 6, w = i & 63;
        int kc = w >> 3, rem = w & 7;
        int q = rem >> 2, t4 = rem & 3;
        int j = 2 * w;
        float v0 = w2[cc * C2 + j], v1 = w2[cc * C2 + j + 1];
        __nv_bfloat16 h0 = __float2bfloat16_rn(v0), h1 = __float2bfloat16_rn(v1);
        float l0 = v0 - __bfloat162float(h0), l1 = v1 - __bfloat162float(h1);
        int e_log = kc * 4 + t4;
        int e_phys = e_log ^ ((cc & 1) << 2);
        int idx = cc * 128 + e_phys * 4 + q;
        g_w2q[idx]     = pack_bf16x2(__bfloat162float(h0), __bfloat162float(h1));
        g_w2q[idx + 2] = pack_bf16x2(l0, l1);
    }
    // prescaled depthwise weights and bias
    for (int i = tid; i < C * 9; i += stride) g_dws[i] = DT_C * dc * dw[i];
    for (int i = tid; i < C; i += stride)     g_b2s[i] = DT_C * fmaf(dc, db[i], b2[i]);
}

__global__ __launch_bounds__(NT, 2)
void afe_step_kernel(const float* __restrict__ b1) {
    if (g_done) return;

    extern __shared__ char smc[];
    float* sf  = (float*)(smc + SM_SF);
    u32* sW1q = (u32*)(smc + SM_W1Q);
    u32* sW2q = (u32*)(smc + SM_W2Q);
    float* sb1 = (float*)(smc + SM_B1);
    float* sb2 = (float*)(smc + SM_B2);
    float* sdw = (float*)(smc + SM_DW);
    float* sred = (float*)(smc + SM_RED);

    const float* fin  = g_cur ? g_buf1 : g_buf0;
    float*       fout = g_cur ? g_buf0 : g_buf1;

    const int b  = blockIdx.z;
    const int y0 = blockIdx.y * TILE_H;
    const int x0 = blockIdx.x * TILE_W;
    const int tid = threadIdx.x;
    const int wwid = tid >> 5;
    const int lane = tid & 31;
    const int g2 = lane >> 2;
    const int t4 = lane & 3;

    // ---- stage weights (linear uint4 copies) ----
    {
        uint4* d0 = (uint4*)sW1q; const uint4* s0 = (const uint4*)g_w1q;
        uint4* d1 = (uint4*)sW2q; const uint4* s1 = (const uint4*)g_w2q;
        #pragma unroll
        for (int i = tid; i < 2048; i += NT) { d0[i] = s0[i]; d1[i] = s1[i]; }
    }
    if (tid < C2) sb1[tid] = b1[tid];
    if (tid < C)  sb2[tid] = g_b2s[tid];
    for (int i = tid; i < C * 9; i += NT) sdw[i] = g_dws[i];

    // ---- fp32 halo tile [64][10][18], zero-pad SAME; incremental indexing ----
    {
        int c  = tid / 180;
        int rem = tid - c * 180;
        int rr = rem / 18;
        int xx = rem - rr * 18;
        int i = tid;
        #pragma unroll 5
        for (int it = 0; it < 45; it++) {
            int y = y0 - 1 + rr;
            int x = x0 - 1 + xx;
            float v = 0.0f;
            if ((unsigned)y < H && (unsigned)x < W)
                v = fin[((b * C + c) * H + y) * W + x];
            sf[i] = v;
            // advance by 256 = 1*180 + 4*18 + 4
            i += 256; c += 1; rr += 4; xx += 4;
            if (xx >= 18) { xx -= 18; rr += 1; }
            if (rr >= 10) { rr -= 10; c += 1; }
        }
    }
    __syncthreads();

    // ---- A1 fragments in registers straight from sf ----
    u32 ah[4][4], al[4][4];
    {
        const int pr = (wwid + 1) * 18 + 1;
        #pragma unroll
        for (int kc = 0; kc < 4; kc++) {
            #pragma unroll
            for (int q = 0; q < 2; q++) {
                int c = 16 * kc + 2 * t4 + 8 * q;
                float v00 = sf[c * 180 + pr + g2];
                float v01 = sf[(c + 1) * 180 + pr + g2];
                float v10 = sf[c * 180 + pr + g2 + 8];
                float v11 = sf[(c + 1) * 180 + pr + g2 + 8];
                __nv_bfloat16 h00 = __float2bfloat16_rn(v00);
                __nv_bfloat16 h01 = __float2bfloat16_rn(v01);
                __nv_bfloat16 h10 = __float2bfloat16_rn(v10);
                __nv_bfloat16 h11 = __float2bfloat16_rn(v11);
                ah[kc][2 * q]     = pack_bf16x2(__bfloat162float(h00), __bfloat162float(h01));
                ah[kc][2 * q + 1] = pack_bf16x2(__bfloat162float(h10), __bfloat162float(h11));
                al[kc][2 * q]     = pack_bf16x2(v00 - __bfloat162float(h00), v01 - __bfloat162float(h01));
                al[kc][2 * q + 1] = pack_bf16x2(v10 - __bfloat162float(h10), v11 - __bfloat162float(h11));
            }
        }
    }

    // ---- fused GEMM1 -> gelu -> GEMM2, one 16-j chunk (kc2) at a time ----
    float acc2[8][4];
    #pragma unroll
    for (int nt = 0; nt < 8; nt++)
        #pragma unroll
        for (int e = 0; e < 4; e++) acc2[nt][e] = 0.0f;

    #pragma unroll
    for (int kc2 = 0; kc2 < 8; kc2++) {
        // GEMM1 for the two n-tiles (n = 2*kc2, 2*kc2+1) feeding this chunk
        float acc[2][4];
        #pragma unroll
        for (int t = 0; t < 2; t++)
            #pragma unroll
            for (int e = 0; e < 4; e++) acc[t][e] = 0.0f;

        #pragma unroll
        for (int t = 0; t < 2; t++) {
            const int row = 8 * (2 * kc2 + t) + g2;
            const int rbase = row * 64;
            const int rsw = (row & 1) << 2;
            #pragma unroll
            for (int kc = 0; kc < 4; kc++) {
                int off = rbase + (((kc * 4 + t4) ^ rsw) << 2);
                uint4 wq = *(const uint4*)(sW1q + off);
                mma_bf16(acc[t], ah[kc], wq.x, wq.y);
                mma_bf16(acc[t], ah[kc], wq.z, wq.w);
                mma_bf16(acc[t], al[kc], wq.x, wq.y);
            }
        }

        // gelu + bf16 hi/lo split -> GEMM2 A fragment for this kc2
        u32 a2h[4], a2l[4];
        #pragma unroll
        for (int t = 0; t < 2; t++) {
            const int n = 2 * kc2 + t;
            float bias0 = sb1[8 * n + 2 * t4];
            float bias1 = sb1[8 * n + 2 * t4 + 1];
            float gl0 = gelu_f(acc[t][0] + bias0);
            float gl1 = gelu_f(acc[t][1] + bias1);
            float gl2 = gelu_f(acc[t][2] + bias0);
            float gl3 = gelu_f(acc[t][3] + bias1);
            __nv_bfloat16 h0 = __float2bfloat16_rn(gl0);
            __nv_bfloat16 h1 = __float2bfloat16_rn(gl1);
            __nv_bfloat16 h2 = __float2bfloat16_rn(gl2);
            __nv_bfloat16 h3 = __float2bfloat16_rn(gl3);
            a2h[2 * t]     = pack_bf16x2(__bfloat162float(h0), __bfloat162float(h1));
            a2h[2 * t + 1] = pack_bf16x2(__bfloat162float(h2), __bfloat162float(h3));
            a2l[2 * t]     = pack_bf16x2(gl0 - __bfloat162float(h0), gl1 - __bfloat162float(h1));
            a2l[2 * t + 1] = pack_bf16x2(gl2 - __bfloat162float(h2), gl3 - __bfloat162float(h3));
        }

        // GEMM2 partial: consume this kc2 chunk for all 8 output tiles
        #pragma unroll
        for (int nt = 0; nt < 8; nt++) {
            const int row = 8 * nt + g2;
            const int rbase = row * 128;
            const int rsw = (row & 1) << 2;
            int off = rbase + (((kc2 * 4 + t4) ^ rsw) << 2);
            uint4 wq = *(const uint4*)(sW2q + off);
            mma_bf16(acc2[nt], a2h, wq.x, wq.y);
            mma_bf16(acc2[nt], a2h, wq.z, wq.w);
            mma_bf16(acc2[nt], a2l, wq.x, wq.y);
        }
    }

    // ---- epilogue: depthwise (prescaled) + Euler + |delta| ----
    float lsum = 0.0f;
    #pragma unroll
    for (int nt = 0; nt < 8; nt++) {
        #pragma unroll
        for (int e = 0; e < 2; e++) {
            const int c = 8 * nt + 2 * t4 + e;
            const float* base = sf + c * 180;
            const float wd0 = sdw[c * 9 + 0], wd1 = sdw[c * 9 + 1], wd2 = sdw[c * 9 + 2];
            const float wd3 = sdw[c * 9 + 3], wd4 = sdw[c * 9 + 4], wd5 = sdw[c * 9 + 5];
            const float wd6 = sdw[c * 9 + 6], wd7 = sdw[c * 9 + 7], wd8 = sdw[c * 9 + 8];
            const float b2v = sb2[c];
            #pragma unroll
            for (int half = 0; half < 2; half++) {
                const int col = g2 + 8 * half;
                float s = b2v;
                s = fmaf(wd0, base[(wwid + 0) * 18 + col + 0], s);
                s = fmaf(wd1, base[(wwid + 0) * 18 + col + 1], s);
                s = fmaf(wd2, base[(wwid + 0) * 18 + col + 2], s);
                s = fmaf(wd3, base[(wwid + 1) * 18 + col + 0], s);
                s = fmaf(wd4, base[(wwid + 1) * 18 + col + 1], s);
                s = fmaf(wd5, base[(wwid + 1) * 18 + col + 2], s);
                s = fmaf(wd6, base[(wwid + 2) * 18 + col + 0], s);
                s = fmaf(wd7, base[(wwid + 2) * 18 + col + 1], s);
                s = fmaf(wd8, base[(wwid + 2) * 18 + col + 2], s);
                s = fmaf(DT_C, acc2[nt][2 * half + e], s);
                float fold = base[(wwid + 1) * 18 + col + 1];
                float fnew = fold + s;
                lsum += fabsf(s);
                fout[((b * C + c) * H + (y0 + wwid)) * W + (x0 + col)] = fnew;
            }
        }
    }

    // ---- reduce |delta|; last CTA finalizes the step ----
    #pragma unroll
    for (int off = 16; off > 0; off >>= 1)
        lsum += __shfl_xor_sync(0xFFFFFFFFu, lsum, off);
    if (lane == 0) sred[wwid] = lsum;
    __syncthreads();
    if (tid == 0) {
        float bs = 0.0f;
        #pragma unroll
        for (int i = 0; i < 8; i++) bs += sred[i];
        atomicAdd(&g_sum, (double)bs);
        __threadfence();
        unsigned prev = atomicAdd(&g_count, 1u);
        if (prev == NBLK - 1) {
            __threadfence();
            double mean = g_sum / (double)FIELD_N;
            g_steps += 1;
            if (mean < THRESH_C) g_done = 1;
            g_cur ^= 1;
            g_sum = 0.0;
            g_count = 0u;
            __threadfence();
        }
    }
}

__global__ void afe_output_kernel(float* __restrict__ out, int out_size) {
    const float* f = g_cur ? g_buf1 : g_buf0;
    int tid = blockIdx.x * blockDim.x + threadIdx.x;
    int stride = gridDim.x * blockDim.x;
    float stepsf = (float)g_steps;
    for (int i = tid; i < out_size; i += stride)
        out[i] = (i < FIELD_N) ? f[i] : stepsf;
}

extern "C" void kernel_launch(void* const* d_in, const int* in_sizes, int n_in,
                              void* d_out, int out_size) {
    const float* field  = (const float*)d_in[0];
    const float* dw     = (const float*)d_in[1];
    const float* db     = (const float*)d_in[2];
    const float* w1     = (const float*)d_in[3];
    const float* b1     = (const float*)d_in[4];
    const float* w2     = (const float*)d_in[5];
    const float* b2     = (const float*)d_in[6];
    const float* dcoeff = (const float*)d_in[7];

    cudaFuncSetAttribute(afe_step_kernel,
                         cudaFuncAttributeMaxDynamicSharedMemorySize, SMEM_BYTES);

    afe_init_kernel<<<1024, 256>>>(field);
    afe_prep_weights<<<64, 256>>>(w1, w2, dw, db, b2, dcoeff);

    dim3 grid(W / TILE_W, H / TILE_H, BB);  // (8, 16, 4) = 512 CTAs
    for (int s = 0; s < MAX_STEPS; s++) {
        afe_step_kernel<<<grid, NT, SMEM_BYTES>>>(b1);
    }

    afe_output_kernel<<<2048, 256>>>((float*)d_out, out_size);
}

// round 10
// speedup vs baseline: 1.0076x; 1.0076x over previous
#include <cuda_runtime.h>
#include <cuda_bf16.h>
#include <math.h>

#define BB 4
#define C 64
#define C2 128
#define H 128
#define W 128
#define HW (H*W)
#define FIELD_N (BB*C*HW)
#define TILE_H 8
#define TILE_W 16
#define NT 256
#define NBLK 512
#define MAX_STEPS 50
#define DT_C 0.1f
#define THRESH_C 0.01

// ---- smem byte offsets ----
#define SM_SF     0          // 64*180*4 = 46080 fp32 halo (pitch 180)
#define SM_W1Q    46080      // 32768 (dead after GEMM1)
#define SM_B1     78848      // 512   (dead after gelu)
#define SM_REACT  46080      // 64*130*4 = 33280, overlays W1Q+B1
#define SM_W2Q    79360      // 32768
#define SM_DW     112128     // 64*12*4 = 3072 (padded, prescaled)
#define SM_B2     115200     // 256 (prescaled)
#define SM_RED    115456     // 32
#define SMEM_BYTES 115488

typedef unsigned u32;
typedef unsigned short u16;

__device__ __forceinline__ u32 pack_bf16x2(float lo, float hi) {
    __nv_bfloat162 t = __floats2bfloat162_rn(lo, hi);
    return *reinterpret_cast<u32*>(&t);
}

__device__ __forceinline__ void mma_bf16(float* d, const u32* a, u32 b0, u32 b1) {
    asm volatile(
        "mma.sync.aligned.m16n8k16.row.col.f32.bf16.bf16.f32 "
        "{%0,%1,%2,%3}, {%4,%5,%6,%7}, {%8,%9}, {%0,%1,%2,%3};"
        : "+f"(d[0]), "+f"(d[1]), "+f"(d[2]), "+f"(d[3])
        : "r"(a[0]), "r"(a[1]), "r"(a[2]), "r"(a[3]), "r"(b0), "r"(b1));
}

// gelu(x) with A&S 7.1.26 erf approximation, |erf err| <= 1.5e-7 abs
__device__ __forceinline__ float gelu_f(float x) {
    float ax = fabsf(x) * 0.70710678118654752f;
    float t = __fdividef(1.0f, fmaf(0.3275911f, ax, 1.0f));
    float poly = t * fmaf(t, fmaf(t, fmaf(t, fmaf(t, 1.061405429f, -1.453152027f),
                                          1.421413741f), -0.284496736f), 0.254829592f);
    float e = __expf(-ax * ax);
    float er = fmaf(-poly, e, 1.0f);
    er = copysignf(er, x);
    return 0.5f * x * (1.0f + er);
}

__device__ float g_buf0[FIELD_N];
__device__ float g_buf1[FIELD_N];
__device__ int      g_done;
__device__ int      g_steps;
__device__ int      g_cur;
__device__ double   g_sum;
__device__ unsigned g_count;
// combined uint4 weight entries {bh0, bh1, bl0, bl1}, phase-swizzled
__device__ __align__(16) u32 g_w1q[8192];
__device__ __align__(16) u32 g_w2q[8192];
__device__ __align__(16) float g_dws[C * 12];  // DT*dc*dw, padded 12/ch
__device__ float g_b2s[C];                     // DT*(dc*db + b2)

__global__ void afe_init_kernel(const float* __restrict__ field) {
    int tid = blockIdx.x * blockDim.x + threadIdx.x;
    if (tid == 0) { g_done = 0; g_steps = 0; g_cur = 0; g_sum = 0.0; g_count = 0u; }
    int stride = gridDim.x * blockDim.x;
    for (int i = tid; i < FIELD_N; i += stride) g_buf0[i] = field[i];
}

__global__ void afe_prep_weights(const float* __restrict__ w1, const float* __restrict__ w2,
                                 const float* __restrict__ dw, const float* __restrict__ db,
                                 const float* __restrict__ b2, const float* __restrict__ dcoeff) {
    int tid = blockIdx.x * blockDim.x + threadIdx.x;
    int stride = gridDim.x * blockDim.x;
    float dc = dcoeff[0];
    // W1 [j=128][word w=0..31], word w covers c = 2w, 2w+1; w = 8kc + t4 + 4q
    for (int i = tid; i < C2 * 32; i += stride) {
        int j = i >> 5, w = i & 31;
        int kc = w >> 3, rem = w & 7;
        int q = rem >> 2, t4 = rem & 3;
        int c = 2 * w;
        float v0 = w1[j * C + c], v1 = w1[j * C + c + 1];
        __nv_bfloat16 h0 = __float2bfloat16_rn(v0), h1 = __float2bfloat16_rn(v1);
        float l0 = v0 - __bfloat162float(h0), l1 = v1 - __bfloat162float(h1);
        int e_phys = (kc * 4 + t4) ^ ((j & 1) << 2);
        int idx = j * 64 + e_phys * 4 + q;
        g_w1q[idx]     = pack_bf16x2(__bfloat162float(h0), __bfloat162float(h1));
        g_w1q[idx + 2] = pack_bf16x2(l0, l1);
    }
    // W2 [c=64][word w=0..63], word w covers j = 2w, 2w+1
    for (int i = tid; i < C * 64; i += stride) {
        int cc = i >> 6, w = i & 63;
        int kc = w >> 3, rem = w & 7;
        int q = rem >> 2, t4 = rem & 3;
        int j = 2 * w;
        float v0 = w2[cc * C2 + j], v1 = w2[cc * C2 + j + 1];
        __nv_bfloat16 h0 = __float2bfloat16_rn(v0), h1 = __float2bfloat16_rn(v1);
        float l0 = v0 - __bfloat162float(h0), l1 = v1 - __bfloat162float(h1);
        int e_phys = (kc * 4 + t4) ^ ((cc & 1) << 2);
        int idx = cc * 128 + e_phys * 4 + q;
        g_w2q[idx]     = pack_bf16x2(__bfloat162float(h0), __bfloat162float(h1));
        g_w2q[idx + 2] = pack_bf16x2(l0, l1);
    }
    // prescaled depthwise weights (padded to 12) and bias
    for (int i = tid; i < C * 12; i += stride) {
        int c = i / 12, k = i % 12;
        g_dws[i] = (k < 9) ? DT_C * dc * dw[c * 9 + k] : 0.0f;
    }
    for (int i = tid; i < C; i += stride) g_b2s[i] = DT_C * fmaf(dc, db[i], b2[i]);
}

__global__ __launch_bounds__(NT, 2)
void afe_step_kernel(const float* __restrict__ b1) {
    if (g_done) return;

    extern __shared__ char smc[];
    float* sf  = (float*)(smc + SM_SF);
    u32* sW1q = (u32*)(smc + SM_W1Q);
    u32* sW2q = (u32*)(smc + SM_W2Q);
    float* sb1 = (float*)(smc + SM_B1);
    float* sreact = (float*)(smc + SM_REACT);
    float* sdw = (float*)(smc + SM_DW);
    float* sb2 = (float*)(smc + SM_B2);
    float* sred = (float*)(smc + SM_RED);

    const float* fin  = g_cur ? g_buf1 : g_buf0;
    float*       fout = g_cur ? g_buf0 : g_buf1;

    const int b  = blockIdx.z;
    const int y0 = blockIdx.y * TILE_H;
    const int x0 = blockIdx.x * TILE_W;
    const int tid = threadIdx.x;
    const int wwid = tid >> 5;
    const int lane = tid & 31;
    const int g2 = lane >> 2;
    const int t4 = lane & 3;

    // ---- stage weights (linear uint4 copies) ----
    {
        uint4* d0 = (uint4*)sW1q; const uint4* s0 = (const uint4*)g_w1q;
        uint4* d1 = (uint4*)sW2q; const uint4* s1 = (const uint4*)g_w2q;
        #pragma unroll
        for (int i = tid; i < 2048; i += NT) { d0[i] = s0[i]; d1[i] = s1[i]; }
        uint4* d2 = (uint4*)sdw; const uint4* s2 = (const uint4*)g_dws;
        #pragma unroll
        for (int i = tid; i < 192; i += NT) d2[i] = s2[i];
    }
    if (tid < C2) sb1[tid] = b1[tid];
    if (tid < C)  sb2[tid] = g_b2s[tid];

    // ---- fp32 halo tile [64][10][18], zero-pad SAME; incremental indexing ----
    {
        int c  = tid / 180;
        int rem = tid - c * 180;
        int rr = rem / 18;
        int xx = rem - rr * 18;
        int i = tid;
        #pragma unroll 5
        for (int it = 0; it < 45; it++) {
            int y = y0 - 1 + rr;
            int x = x0 - 1 + xx;
            float v = 0.0f;
            if ((unsigned)y < H && (unsigned)x < W)
                v = fin[((b * C + c) * H + y) * W + x];
            sf[i] = v;
            i += 256; c += 1; rr += 4; xx += 4;
            if (xx >= 18) { xx -= 18; rr += 1; }
            if (rr >= 10) { rr -= 10; c += 1; }
        }
    }
    __syncthreads();

    // ---- A1 fragments in registers straight from sf ----
    u32 ah[4][4], al[4][4];
    {
        const int pr = (wwid + 1) * 18 + 1;
        #pragma unroll
        for (int kc = 0; kc < 4; kc++) {
            #pragma unroll
            for (int q = 0; q < 2; q++) {
                int c = 16 * kc + 2 * t4 + 8 * q;
                float v00 = sf[c * 180 + pr + g2];
                float v01 = sf[(c + 1) * 180 + pr + g2];
                float v10 = sf[c * 180 + pr + g2 + 8];
                float v11 = sf[(c + 1) * 180 + pr + g2 + 8];
                __nv_bfloat16 h00 = __float2bfloat16_rn(v00);
                __nv_bfloat16 h01 = __float2bfloat16_rn(v01);
                __nv_bfloat16 h10 = __float2bfloat16_rn(v10);
                __nv_bfloat16 h11 = __float2bfloat16_rn(v11);
                ah[kc][2 * q]     = pack_bf16x2(__bfloat162float(h00), __bfloat162float(h01));
                ah[kc][2 * q + 1] = pack_bf16x2(__bfloat162float(h10), __bfloat162float(h11));
                al[kc][2 * q]     = pack_bf16x2(v00 - __bfloat162float(h00), v01 - __bfloat162float(h01));
                al[kc][2 * q + 1] = pack_bf16x2(v10 - __bfloat162float(h10), v11 - __bfloat162float(h11));
            }
        }
    }

    // ---- GEMM1 (two N-halves) + gelu -> GEMM2 A fragments ----
    u32 a2h[8][4], a2l[8][4];
    #pragma unroll
    for (int hh = 0; hh < 2; hh++) {
        float acc[8][4];
        #pragma unroll
        for (int ntl = 0; ntl < 8; ntl++)
            #pragma unroll
            for (int e = 0; e < 4; e++) acc[ntl][e] = 0.0f;

        #pragma unroll
        for (int ntl = 0; ntl < 8; ntl++) {
            const int row = 8 * (8 * hh + ntl) + g2;
            const int rbase = row * 64;
            const int rsw = (row & 1) << 2;
            #pragma unroll
            for (int kc = 0; kc < 4; kc++) {
                int off = rbase + (((kc * 4 + t4) ^ rsw) << 2);
                uint4 wq = *(const uint4*)(sW1q + off);
                mma_bf16(acc[ntl], ah[kc], wq.x, wq.y);
                mma_bf16(acc[ntl], ah[kc], wq.z, wq.w);
                mma_bf16(acc[ntl], al[kc], wq.x, wq.y);
            }
        }

        #pragma unroll
        for (int ntl = 0; ntl < 8; ntl++) {
            const int n = 8 * hh + ntl;
            float bias0 = sb1[8 * n + 2 * t4];
            float bias1 = sb1[8 * n + 2 * t4 + 1];
            float gl0 = gelu_f(acc[ntl][0] + bias0);
            float gl1 = gelu_f(acc[ntl][1] + bias1);
            float gl2 = gelu_f(acc[ntl][2] + bias0);
            float gl3 = gelu_f(acc[ntl][3] + bias1);
            __nv_bfloat16 h0 = __float2bfloat16_rn(gl0);
            __nv_bfloat16 h1 = __float2bfloat16_rn(gl1);
            __nv_bfloat16 h2 = __float2bfloat16_rn(gl2);
            __nv_bfloat16 h3 = __float2bfloat16_rn(gl3);
            int kc2 = n >> 1;
            int q  = (n & 1) << 1;
            a2h[kc2][q]     = pack_bf16x2(__bfloat162float(h0), __bfloat162float(h1));
            a2h[kc2][q + 1] = pack_bf16x2(__bfloat162float(h2), __bfloat162float(h3));
            a2l[kc2][q]     = pack_bf16x2(gl0 - __bfloat162float(h0), gl1 - __bfloat162float(h1));
            a2l[kc2][q + 1] = pack_bf16x2(gl2 - __bfloat162float(h2), gl3 - __bfloat162float(h3));
        }
    }
    __syncthreads();   // W1Q/B1 now dead in ALL warps; react may overlay

    // ---- GEMM2 ----
    float acc2[8][4];
    #pragma unroll
    for (int nt = 0; nt < 8; nt++)
        #pragma unroll
        for (int e = 0; e < 4; e++) acc2[nt][e] = 0.0f;

    #pragma unroll
    for (int nt = 0; nt < 8; nt++) {
        const int row = 8 * nt + g2;
        const int rbase = row * 128;
        const int rsw = (row & 1) << 2;
        #pragma unroll
        for (int kc = 0; kc < 8; kc++) {
            int off = rbase + (((kc * 4 + t4) ^ rsw) << 2);
            uint4 wq = *(const uint4*)(sW2q + off);
            mma_bf16(acc2[nt], a2h[kc], wq.x, wq.y);
            mma_bf16(acc2[nt], a2h[kc], wq.z, wq.w);
            mma_bf16(acc2[nt], a2l[kc], wq.x, wq.y);
        }
    }

    // ---- store react = DT*acc2 + b2s into smem [c][130] ----
    {
        const int p0 = 16 * wwid + g2;
        #pragma unroll
        for (int nt = 0; nt < 8; nt++) {
            const int cb = 8 * nt + 2 * t4;
            float b20 = sb2[cb], b21 = sb2[cb + 1];
            sreact[cb * 130 + p0]           = fmaf(DT_C, acc2[nt][0], b20);
            sreact[(cb + 1) * 130 + p0]     = fmaf(DT_C, acc2[nt][1], b21);
            sreact[cb * 130 + p0 + 8]       = fmaf(DT_C, acc2[nt][2], b20);
            sreact[(cb + 1) * 130 + p0 + 8] = fmaf(DT_C, acc2[nt][3], b21);
        }
    }
    __syncthreads();

    // ---- epilogue: warp w owns channels 8w..8w+7; lane owns 4 consecutive px ----
    float lsum = 0.0f;
    {
        const int r    = lane >> 2;        // tile row 0..7
        const int colb = 4 * (lane & 3);   // tile col base 0,4,8,12
        const int gbase = ((b * C) * H + (y0 + r)) * W + (x0 + colb);
        #pragma unroll
        for (int ic = 0; ic < 8; ic++) {
            const int c = 8 * wwid + ic;
            const float* bp = sf + c * 180;
            // halo rows r..r+2, cols colb..colb+5 via float2
            float2 h00 = *(const float2*)(bp + r * 18 + colb);
            float2 h01 = *(const float2*)(bp + r * 18 + colb + 2);
            float2 h02 = *(const float2*)(bp + r * 18 + colb + 4);
            float2 h10 = *(const float2*)(bp + (r + 1) * 18 + colb);
            float2 h11 = *(const float2*)(bp + (r + 1) * 18 + colb + 2);
            float2 h12 = *(const float2*)(bp + (r + 1) * 18 + colb + 4);
            float2 h20 = *(const float2*)(bp + (r + 2) * 18 + colb);
            float2 h21 = *(const float2*)(bp + (r + 2) * 18 + colb + 2);
            float2 h22 = *(const float2*)(bp + (r + 2) * 18 + colb + 4);
            float v0[6] = {h00.x, h00.y, h01.x, h01.y, h02.x, h02.y};
            float v1[6] = {h10.x, h10.y, h11.x, h11.y, h12.x, h12.y};
            float v2[6] = {h20.x, h20.y, h21.x, h21.y, h22.x, h22.y};
            float4 w0 = *(const float4*)(sdw + c * 12);
            float4 w1v = *(const float4*)(sdw + c * 12 + 4);
            float4 w2v = *(const float4*)(sdw + c * 12 + 8);
            float2 rc0 = *(const float2*)(sreact + c * 130 + 4 * (lane & 3) + 16 * r);
            float2 rc1 = *(const float2*)(sreact + c * 130 + 4 * (lane & 3) + 16 * r + 2);
            float react[4] = {rc0.x, rc0.y, rc1.x, rc1.y};
            float4 ov;
            float* ovp = (float*)&ov;
            #pragma unroll
            for (int k = 0; k < 4; k++) {
                float s = react[k];
                s = fmaf(w0.x, v0[k],     s);
                s = fmaf(w0.y, v0[k + 1], s);
                s = fmaf(w0.z, v0[k + 2], s);
                s = fmaf(w0.w, v1[k],     s);
                s = fmaf(w1v.x, v1[k + 1], s);
                s = fmaf(w1v.y, v1[k + 2], s);
                s = fmaf(w1v.z, v2[k],     s);
                s = fmaf(w1v.w, v2[k + 1], s);
                s = fmaf(w2v.x, v2[k + 2], s);
                lsum += fabsf(s);
                ovp[k] = v1[k + 1] + s;
            }
            *(float4*)(fout + gbase + c * HW) = ov;
        }
    }

    // ---- reduce |delta|; last CTA finalizes the step ----
    #pragma unroll
    for (int off = 16; off > 0; off >>= 1)
        lsum += __shfl_xor_sync(0xFFFFFFFFu, lsum, off);
    if (lane == 0) sred[wwid] = lsum;
    __syncthreads();
    if (tid == 0) {
        float bs = 0.0f;
        #pragma unroll
        for (int i = 0; i < 8; i++) bs += sred[i];
        atomicAdd(&g_sum, (double)bs);
        __threadfence();
        unsigned prev = atomicAdd(&g_count, 1u);
        if (prev == NBLK - 1) {
            __threadfence();
            double mean = g_sum / (double)FIELD_N;
            g_steps += 1;
            if (mean < THRESH_C) g_done = 1;
            g_cur ^= 1;
            g_sum = 0.0;
            g_count = 0u;
            __threadfence();
        }
    }
}

__global__ void afe_output_kernel(float* __restrict__ out, int out_size) {
    const float* f = g_cur ? g_buf1 : g_buf0;
    int tid = blockIdx.x * blockDim.x + threadIdx.x;
    int stride = gridDim.x * blockDim.x;
    float stepsf = (float)g_steps;
    for (int i = tid; i < out_size; i += stride)
        out[i] = (i < FIELD_N) ? f[i] : stepsf;
}

extern "C" void kernel_launch(void* const* d_in, const int* in_sizes, int n_in,
                              void* d_out, int out_size) {
    const float* field  = (const float*)d_in[0];
    const float* dw     = (const float*)d_in[1];
    const float* db     = (const float*)d_in[2];
    const float* w1     = (const float*)d_in[3];
    const float* b1     = (const float*)d_in[4];
    const float* w2     = (const float*)d_in[5];
    const float* b2     = (const float*)d_in[6];
    const float* dcoeff = (const float*)d_in[7];

    cudaFuncSetAttribute(afe_step_kernel,
                         cudaFuncAttributeMaxDynamicSharedMemorySize, SMEM_BYTES);

    afe_init_kernel<<<1024, 256>>>(field);
    afe_prep_weights<<<64, 256>>>(w1, w2, dw, db, b2, dcoeff);

    dim3 grid(W / TILE_W, H / TILE_H, BB);  // (8, 16, 4) = 512 CTAs
    for (int s = 0; s < MAX_STEPS; s++) {
        afe_step_kernel<<<grid, NT, SMEM_BYTES>>>(b1);
    }

    afe_output_kernel<<<2048, 256>>>((float*)d_out, out_size);
}

// round 11
// speedup vs baseline: 1.0399x; 1.0320x over previous
#include <cuda_runtime.h>
#include <cuda_bf16.h>
#include <math.h>

#define BB 4
#define C 64
#define C2 128
#define H 128
#define W 128
#define HW (H*W)
#define FIELD_N (BB*C*HW)
#define TILE_H 8
#define TILE_W 16
#define NT 256
#define NBLK 512
#define MAX_STEPS 50
#define DT_C 0.1f
#define THRESH_C 0.01

// ---- smem byte offsets ----
#define SM_SF   0          // 64*180*4 = 46080 fp32 halo
#define SM_W1Q  46080      // 32768 (128 rows x 16 uint4 entries)
#define SM_W2Q  78848      // 32768 (64 rows x 32 uint4 entries)
#define SM_B1   111616     // 512
#define SM_B2   112128     // 256  (prescaled)
#define SM_DW   112640     // 2304 (prescaled)
#define SM_RED  114944     // 32
#define SMEM_BYTES 114976

typedef unsigned u32;
typedef unsigned short u16;

__device__ __forceinline__ u32 pack_bf16x2(float lo, float hi) {
    __nv_bfloat162 t = __floats2bfloat162_rn(lo, hi);
    return *reinterpret_cast<u32*>(&t);
}

// truncation split: hi = top-16-bits of x (exact residual lo = x - hi)
__device__ __forceinline__ float hi_trunc(float x) {
    return __uint_as_float(__float_as_uint(x) & 0xFFFF0000u);
}
// pack truncated-bf16(x0), truncated-bf16(x1) into one u32 (x0 in low half)
__device__ __forceinline__ u32 pack_trunc(float x0, float x1) {
    return __byte_perm(__float_as_uint(x0), __float_as_uint(x1), 0x7632);
}

__device__ __forceinline__ void mma_bf16(float* d, const u32* a, u32 b0, u32 b1) {
    asm volatile(
        "mma.sync.aligned.m16n8k16.row.col.f32.bf16.bf16.f32 "
        "{%0,%1,%2,%3}, {%4,%5,%6,%7}, {%8,%9}, {%0,%1,%2,%3};"
        : "+f"(d[0]), "+f"(d[1]), "+f"(d[2]), "+f"(d[3])
        : "r"(a[0]), "r"(a[1]), "r"(a[2]), "r"(a[3]), "r"(b0), "r"(b1));
}

// gelu(x) with A&S 7.1.26 erf approximation, |erf err| <= 1.5e-7 abs
__device__ __forceinline__ float gelu_f(float x) {
    float ax = fabsf(x) * 0.70710678118654752f;
    float t = __fdividef(1.0f, fmaf(0.3275911f, ax, 1.0f));
    float poly = t * fmaf(t, fmaf(t, fmaf(t, fmaf(t, 1.061405429f, -1.453152027f),
                                          1.421413741f), -0.284496736f), 0.254829592f);
    float e = __expf(-ax * ax);
    float er = fmaf(-poly, e, 1.0f);
    er = copysignf(er, x);
    return 0.5f * x * (1.0f + er);
}

__device__ float g_buf0[FIELD_N];
__device__ float g_buf1[FIELD_N];
__device__ int      g_done;
__device__ int      g_steps;
__device__ int      g_cur;
__device__ double   g_sum;
__device__ unsigned g_count;
// combined uint4 weight entries {bh0, bh1, bl0, bl1}, phase-swizzled
__device__ __align__(16) u32 g_w1q[8192];
__device__ __align__(16) u32 g_w2q[8192];
__device__ float g_dws[C * 9];   // DT*dc*dw
__device__ float g_b2s[C];       // DT*(dc*db + b2)

__global__ void afe_init_kernel(const float* __restrict__ field) {
    int tid = blockIdx.x * blockDim.x + threadIdx.x;
    if (tid == 0) { g_done = 0; g_steps = 0; g_cur = 0; g_sum = 0.0; g_count = 0u; }
    int stride = gridDim.x * blockDim.x;
    for (int i = tid; i < FIELD_N; i += stride) g_buf0[i] = field[i];
}

__global__ void afe_prep_weights(const float* __restrict__ w1, const float* __restrict__ w2,
                                 const float* __restrict__ dw, const float* __restrict__ db,
                                 const float* __restrict__ b2, const float* __restrict__ dcoeff) {
    int tid = blockIdx.x * blockDim.x + threadIdx.x;
    int stride = gridDim.x * blockDim.x;
    float dc = dcoeff[0];
    // W1 [j=128][word w=0..31], word w covers c = 2w, 2w+1; w = 8kc + t4 + 4q
    for (int i = tid; i < C2 * 32; i += stride) {
        int j = i >> 5, w = i & 31;
        int kc = w >> 3, rem = w & 7;
        int q = rem >> 2, t4 = rem & 3;
        int c = 2 * w;
        float v0 = w1[j * C + c], v1 = w1[j * C + c + 1];
        __nv_bfloat16 h0 = __float2bfloat16_rn(v0), h1 = __float2bfloat16_rn(v1);
        float l0 = v0 - __bfloat162float(h0), l1 = v1 - __bfloat162float(h1);
        int e_phys = (kc * 4 + t4) ^ ((j & 1) << 2);
        int idx = j * 64 + e_phys * 4 + q;
        g_w1q[idx]     = pack_bf16x2(__bfloat162float(h0), __bfloat162float(h1));
        g_w1q[idx + 2] = pack_bf16x2(l0, l1);
    }
    // W2 [c=64][word w=0..63], word w covers j = 2w, 2w+1
    for (int i = tid; i < C * 64; i += stride) {
        int cc = i >> 6, w = i & 63;
        int kc = w >> 3, rem = w & 7;
        int q = rem >> 2, t4 = rem & 3;
        int j = 2 * w;
        float v0 = w2[cc * C2 + j], v1 = w2[cc * C2 + j + 1];
        __nv_bfloat16 h0 = __float2bfloat16_rn(v0), h1 = __float2bfloat16_rn(v1);
        float l0 = v0 - __bfloat162float(h0), l1 = v1 - __bfloat162float(h1);
        int e_phys = (kc * 4 + t4) ^ ((cc & 1) << 2);
        int idx = cc * 128 + e_phys * 4 + q;
        g_w2q[idx]     = pack_bf16x2(__bfloat162float(h0), __bfloat162float(h1));
        g_w2q[idx + 2] = pack_bf16x2(l0, l1);
    }
    // prescaled depthwise weights and bias
    for (int i = tid; i < C * 9; i += stride) g_dws[i] = DT_C * dc * dw[i];
    for (int i = tid; i < C; i += stride)     g_b2s[i] = DT_C * fmaf(dc, db[i], b2[i]);
}

__global__ __launch_bounds__(NT, 2)
void afe_step_kernel(const float* __restrict__ b1) {
    if (g_done) return;

    extern __shared__ char smc[];
    float* sf  = (float*)(smc + SM_SF);
    u32* sW1q = (u32*)(smc + SM_W1Q);
    u32* sW2q = (u32*)(smc + SM_W2Q);
    float* sb1 = (float*)(smc + SM_B1);
    float* sb2 = (float*)(smc + SM_B2);
    float* sdw = (float*)(smc + SM_DW);
    float* sred = (float*)(smc + SM_RED);

    const float* fin  = g_cur ? g_buf1 : g_buf0;
    float*       fout = g_cur ? g_buf0 : g_buf1;

    const int b  = blockIdx.z;
    const int y0 = blockIdx.y * TILE_H;
    const int x0 = blockIdx.x * TILE_W;
    const int tid = threadIdx.x;
    const int wwid = tid >> 5;
    const int lane = tid & 31;
    const int g2 = lane >> 2;
    const int t4 = lane & 3;

    // ---- stage weights (linear uint4 copies) ----
    {
        uint4* d0 = (uint4*)sW1q; const uint4* s0 = (const uint4*)g_w1q;
        uint4* d1 = (uint4*)sW2q; const uint4* s1 = (const uint4*)g_w2q;
        #pragma unroll
        for (int i = tid; i < 2048; i += NT) { d0[i] = s0[i]; d1[i] = s1[i]; }
    }
    if (tid < C2) sb1[tid] = b1[tid];
    if (tid < C)  sb2[tid] = g_b2s[tid];
    for (int i = tid; i < C * 9; i += NT) sdw[i] = g_dws[i];

    // ---- fp32 halo tile [64][10][18], zero-pad SAME; incremental indexing ----
    {
        int c  = tid / 180;
        int rem = tid - c * 180;
        int rr = rem / 18;
        int xx = rem - rr * 18;
        int i = tid;
        #pragma unroll 5
        for (int it = 0; it < 45; it++) {
            int y = y0 - 1 + rr;
            int x = x0 - 1 + xx;
            float v = 0.0f;
            if ((unsigned)y < H && (unsigned)x < W)
                v = fin[((b * C + c) * H + y) * W + x];
            sf[i] = v;
            i += 256; c += 1; rr += 4; xx += 4;
            if (xx >= 18) { xx -= 18; rr += 1; }
            if (rr >= 10) { rr -= 10; c += 1; }
        }
    }
    __syncthreads();

    // ---- A1 fragments in registers straight from sf (truncation split) ----
    u32 ah[4][4], al[4][4];
    {
        const int pr = (wwid + 1) * 18 + 1;
        #pragma unroll
        for (int kc = 0; kc < 4; kc++) {
            #pragma unroll
            for (int q = 0; q < 2; q++) {
                int c = 16 * kc + 2 * t4 + 8 * q;
                float v00 = sf[c * 180 + pr + g2];
                float v01 = sf[(c + 1) * 180 + pr + g2];
                float v10 = sf[c * 180 + pr + g2 + 8];
                float v11 = sf[(c + 1) * 180 + pr + g2 + 8];
                ah[kc][2 * q]     = pack_trunc(v00, v01);
                ah[kc][2 * q + 1] = pack_trunc(v10, v11);
                al[kc][2 * q]     = pack_trunc(v00 - hi_trunc(v00), v01 - hi_trunc(v01));
                al[kc][2 * q + 1] = pack_trunc(v10 - hi_trunc(v10), v11 - hi_trunc(v11));
            }
        }
    }

    // ---- GEMM1 half -> gelu -> GEMM2 half, per hh; acc2 order preserved ----
    float acc2[8][4];
    #pragma unroll
    for (int nt = 0; nt < 8; nt++)
        #pragma unroll
        for (int e = 0; e < 4; e++) acc2[nt][e] = 0.0f;

    #pragma unroll
    for (int hh = 0; hh < 2; hh++) {
        float acc[8][4];
        #pragma unroll
        for (int ntl = 0; ntl < 8; ntl++)
            #pragma unroll
            for (int e = 0; e < 4; e++) acc[ntl][e] = 0.0f;

        #pragma unroll
        for (int ntl = 0; ntl < 8; ntl++) {
            const int row = 8 * (8 * hh + ntl) + g2;
            const int rbase = row * 64;
            const int rsw = (row & 1) << 2;
            #pragma unroll
            for (int kc = 0; kc < 4; kc++) {
                int off = rbase + (((kc * 4 + t4) ^ rsw) << 2);
                uint4 wq = *(const uint4*)(sW1q + off);
                mma_bf16(acc[ntl], ah[kc], wq.x, wq.y);
                mma_bf16(acc[ntl], ah[kc], wq.z, wq.w);
                mma_bf16(acc[ntl], al[kc], wq.x, wq.y);
            }
        }

        // gelu + truncation split -> a2 fragments for kc2 = 4hh .. 4hh+3
        u32 a2h[4][4], a2l[4][4];
        #pragma unroll
        for (int ntl = 0; ntl < 8; ntl++) {
            const int n = 8 * hh + ntl;
            float bias0 = sb1[8 * n + 2 * t4];
            float bias1 = sb1[8 * n + 2 * t4 + 1];
            float gl0 = gelu_f(acc[ntl][0] + bias0);
            float gl1 = gelu_f(acc[ntl][1] + bias1);
            float gl2 = gelu_f(acc[ntl][2] + bias0);
            float gl3 = gelu_f(acc[ntl][3] + bias1);
            int kcl = ntl >> 1;
            int q   = (ntl & 1) << 1;
            a2h[kcl][q]     = pack_trunc(gl0, gl1);
            a2h[kcl][q + 1] = pack_trunc(gl2, gl3);
            a2l[kcl][q]     = pack_trunc(gl0 - hi_trunc(gl0), gl1 - hi_trunc(gl1));
            a2l[kcl][q + 1] = pack_trunc(gl2 - hi_trunc(gl2), gl3 - hi_trunc(gl3));
        }

        // GEMM2 partial over this half's 4 k-chunks (kc = 4hh + kcl)
        #pragma unroll
        for (int nt = 0; nt < 8; nt++) {
            const int row = 8 * nt + g2;
            const int rbase = row * 128;
            const int rsw = (row & 1) << 2;
            #pragma unroll
            for (int kcl = 0; kcl < 4; kcl++) {
                int kc = 4 * hh + kcl;
                int off = rbase + (((kc * 4 + t4) ^ rsw) << 2);
                uint4 wq = *(const uint4*)(sW2q + off);
                mma_bf16(acc2[nt], a2h[kcl], wq.x, wq.y);
                mma_bf16(acc2[nt], a2h[kcl], wq.z, wq.w);
                mma_bf16(acc2[nt], a2l[kcl], wq.x, wq.y);
            }
        }
    }

    // ---- epilogue: depthwise (prescaled) + Euler + |delta| ----
    float lsum = 0.0f;
    #pragma unroll
    for (int nt = 0; nt < 8; nt++) {
        #pragma unroll
        for (int e = 0; e < 2; e++) {
            const int c = 8 * nt + 2 * t4 + e;
            const float* base = sf + c * 180;
            const float wd0 = sdw[c * 9 + 0], wd1 = sdw[c * 9 + 1], wd2 = sdw[c * 9 + 2];
            const float wd3 = sdw[c * 9 + 3], wd4 = sdw[c * 9 + 4], wd5 = sdw[c * 9 + 5];
            const float wd6 = sdw[c * 9 + 6], wd7 = sdw[c * 9 + 7], wd8 = sdw[c * 9 + 8];
            const float b2v = sb2[c];
            #pragma unroll
            for (int half = 0; half < 2; half++) {
                const int col = g2 + 8 * half;
                float s = b2v;
                s = fmaf(wd0, base[(wwid + 0) * 18 + col + 0], s);
                s = fmaf(wd1, base[(wwid + 0) * 18 + col + 1], s);
                s = fmaf(wd2, base[(wwid + 0) * 18 + col + 2], s);
                s = fmaf(wd3, base[(wwid + 1) * 18 + col + 0], s);
                s = fmaf(wd4, base[(wwid + 1) * 18 + col + 1], s);
                s = fmaf(wd5, base[(wwid + 1) * 18 + col + 2], s);
                s = fmaf(wd6, base[(wwid + 2) * 18 + col + 0], s);
                s = fmaf(wd7, base[(wwid + 2) * 18 + col + 1], s);
                s = fmaf(wd8, base[(wwid + 2) * 18 + col + 2], s);
                s = fmaf(DT_C, acc2[nt][2 * half + e], s);
                float fold = base[(wwid + 1) * 18 + col + 1];
                float fnew = fold + s;
                lsum += fabsf(s);
                fout[((b * C + c) * H + (y0 + wwid)) * W + (x0 + col)] = fnew;
            }
        }
    }

    // ---- reduce |delta|; last CTA finalizes the step ----
    #pragma unroll
    for (int off = 16; off > 0; off >>= 1)
        lsum += __shfl_xor_sync(0xFFFFFFFFu, lsum, off);
    if (lane == 0) sred[wwid] = lsum;
    __syncthreads();
    if (tid == 0) {
        float bs = 0.0f;
        #pragma unroll
        for (int i = 0; i < 8; i++) bs += sred[i];
        atomicAdd(&g_sum, (double)bs);
        __threadfence();
        unsigned prev = atomicAdd(&g_count, 1u);
        if (prev == NBLK - 1) {
            __threadfence();
            double mean = g_sum / (double)FIELD_N;
            g_steps += 1;
            if (mean < THRESH_C) g_done = 1;
            g_cur ^= 1;
            g_sum = 0.0;
            g_count = 0u;
            __threadfence();
        }
    }
}

__global__ void afe_output_kernel(float* __restrict__ out, int out_size) {
    const float* f = g_cur ? g_buf1 : g_buf0;
    int tid = blockIdx.x * blockDim.x + threadIdx.x;
    int stride = gridDim.x * blockDim.x;
    float stepsf = (float)g_steps;
    for (int i = tid; i < out_size; i += stride)
        out[i] = (i < FIELD_N) ? f[i] : stepsf;
}

extern "C" void kernel_launch(void* const* d_in, const int* in_sizes, int n_in,
                              void* d_out, int out_size) {
    const float* field  = (const float*)d_in[0];
    const float* dw     = (const float*)d_in[1];
    const float* db     = (const float*)d_in[2];
    const float* w1     = (const float*)d_in[3];
    const float* b1     = (const float*)d_in[4];
    const float* w2     = (const float*)d_in[5];
    const float* b2     = (const float*)d_in[6];
    const float* dcoeff = (const float*)d_in[7];

    cudaFuncSetAttribute(afe_step_kernel,
                         cudaFuncAttributeMaxDynamicSharedMemorySize, SMEM_BYTES);

    afe_init_kernel<<<1024, 256>>>(field);
    afe_prep_weights<<<64, 256>>>(w1, w2, dw, db, b2, dcoeff);

    dim3 grid(W / TILE_W, H / TILE_H, BB);  // (8, 16, 4) = 512 CTAs
    for (int s = 0; s < MAX_STEPS; s++) {
        afe_step_kernel<<<grid, NT, SMEM_BYTES>>>(b1);
    }

    afe_output_kernel<<<2048, 256>>>((float*)d_out, out_size);
}

// round 13
// speedup vs baseline: 1.0915x; 1.0497x over previous
#include <cuda_runtime.h>
#include <cuda_bf16.h>
#include <math.h>

#define BB 4
#define C 64
#define C2 128
#define H 128
#define W 128
#define HW (H*W)
#define FIELD_N (BB*C*HW)
#define TILE_H 8
#define TILE_W 16
#define NT 256
#define NBLK 512
#define MAX_STEPS 50
#define DT_C 0.1f
#define THRESH_C 0.01

// ---- smem byte offsets ----
#define SM_SF   0          // 64*180*4 = 46080 fp32 halo
#define SM_W1Q  46080      // 32768 (128 rows x 16 uint4 entries)
#define SM_W2Q  78848      // 32768 (64 rows x 32 uint4 entries)
#define SM_B1   111616     // 512
#define SM_B2   112128     // 256  (prescaled)
#define SM_DW   112640     // 2304 (prescaled)
#define SM_RED  114944     // 32
#define SMEM_BYTES 114976

typedef unsigned u32;
typedef unsigned short u16;

__device__ __forceinline__ u32 pack_bf16x2(float lo, float hi) {
    __nv_bfloat162 t = __floats2bfloat162_rn(lo, hi);
    return *reinterpret_cast<u32*>(&t);
}

// truncation split: hi = top-16-bits of x (exact residual lo = x - hi)
__device__ __forceinline__ float hi_trunc(float x) {
    return __uint_as_float(__float_as_uint(x) & 0xFFFF0000u);
}
__device__ __forceinline__ u32 pack_trunc(float x0, float x1) {
    return __byte_perm(__float_as_uint(x0), __float_as_uint(x1), 0x7632);
}

__device__ __forceinline__ void mma_bf16(float* d, const u32* a, u32 b0, u32 b1) {
    asm volatile(
        "mma.sync.aligned.m16n8k16.row.col.f32.bf16.bf16.f32 "
        "{%0,%1,%2,%3}, {%4,%5,%6,%7}, {%8,%9}, {%0,%1,%2,%3};"
        : "+f"(d[0]), "+f"(d[1]), "+f"(d[2]), "+f"(d[3])
        : "r"(a[0]), "r"(a[1]), "r"(a[2]), "r"(a[3]), "r"(b0), "r"(b1));
}

__device__ __forceinline__ void cp16(u32 saddr, const void* g) {
    asm volatile("cp.async.ca.shared.global [%0], [%1], 16;" :: "r"(saddr), "l"(g));
}

// gelu(x) with A&S 7.1.26 erf approximation
__device__ __forceinline__ float gelu_f(float x) {
    float ax = fabsf(x) * 0.70710678118654752f;
    float t = __fdividef(1.0f, fmaf(0.3275911f, ax, 1.0f));
    float poly = t * fmaf(t, fmaf(t, fmaf(t, fmaf(t, 1.061405429f, -1.453152027f),
                                          1.421413741f), -0.284496736f), 0.254829592f);
    float e = __expf(-ax * ax);
    float er = fmaf(-poly, e, 1.0f);
    er = copysignf(er, x);
    return 0.5f * x * (1.0f + er);
}

__device__ float g_buf0[FIELD_N];
__device__ float g_buf1[FIELD_N];
__device__ int      g_done;
__device__ int      g_steps;
__device__ int      g_cur;
__device__ double   g_sum;
__device__ unsigned g_count;
__device__ __align__(16) u32 g_w1q[8192];
__device__ __align__(16) u32 g_w2q[8192];
__device__ __align__(16) float g_dws[C * 9];   // DT*dc*dw
__device__ __align__(16) float g_b2s[C];       // DT*(dc*db + b2)
__device__ __align__(16) float g_b1c[C2];      // copy of b1 (16B-aligned for cp.async)

__global__ void afe_init_kernel(const float* __restrict__ field) {
    int tid = blockIdx.x * blockDim.x + threadIdx.x;
    if (tid == 0) { g_done = 0; g_steps = 0; g_cur = 0; g_sum = 0.0; g_count = 0u; }
    int stride = gridDim.x * blockDim.x;
    for (int i = tid; i < FIELD_N; i += stride) g_buf0[i] = field[i];
}

__global__ void afe_prep_weights(const float* __restrict__ w1, const float* __restrict__ w2,
                                 const float* __restrict__ dw, const float* __restrict__ db,
                                 const float* __restrict__ b1, const float* __restrict__ b2,
                                 const float* __restrict__ dcoeff) {
    int tid = blockIdx.x * blockDim.x + threadIdx.x;
    int stride = gridDim.x * blockDim.x;
    float dc = dcoeff[0];
    for (int i = tid; i < C2 * 32; i += stride) {
        int j = i >> 5, w = i & 31;
        int kc = w >> 3, rem = w & 7;
        int q = rem >> 2, t4 = rem & 3;
        int c = 2 * w;
        float v0 = w1[j * C + c], v1 = w1[j * C + c + 1];
        __nv_bfloat16 h0 = __float2bfloat16_rn(v0), h1 = __float2bfloat16_rn(v1);
        float l0 = v0 - __bfloat162float(h0), l1 = v1 - __bfloat162float(h1);
        int e_phys = (kc * 4 + t4) ^ ((j & 1) << 2);
        int idx = j * 64 + e_phys * 4 + q;
        g_w1q[idx]     = pack_bf16x2(__bfloat162float(h0), __bfloat162float(h1));
        g_w1q[idx + 2] = pack_bf16x2(l0, l1);
    }
    for (int i = tid; i < C * 64; i += stride) {
        int cc = i >> 6, w = i & 63;
        int kc = w >> 3, rem = w & 7;
        int q = rem >> 2, t4 = rem & 3;
        int j = 2 * w;
        float v0 = w2[cc * C2 + j], v1 = w2[cc * C2 + j + 1];
        __nv_bfloat16 h0 = __float2bfloat16_rn(v0), h1 = __float2bfloat16_rn(v1);
        float l0 = v0 - __bfloat162float(h0), l1 = v1 - __bfloat162float(h1);
        int e_phys = (kc * 4 + t4) ^ ((cc & 1) << 2);
        int idx = cc * 128 + e_phys * 4 + q;
        g_w2q[idx]     = pack_bf16x2(__bfloat162float(h0), __bfloat162float(h1));
        g_w2q[idx + 2] = pack_bf16x2(l0, l1);
    }
    for (int i = tid; i < C * 9; i += stride) g_dws[i] = DT_C * dc * dw[i];
    for (int i = tid; i < C; i += stride)     g_b2s[i] = DT_C * fmaf(dc, db[i], b2[i]);
    for (int i = tid; i < C2; i += stride)    g_b1c[i] = b1[i];
}

__global__ __launch_bounds__(NT, 2)
void afe_step_kernel() {
    if (g_done) return;

    extern __shared__ char smc[];
    float* sf  = (float*)(smc + SM_SF);
    u32* sW1q = (u32*)(smc + SM_W1Q);
    u32* sW2q = (u32*)(smc + SM_W2Q);
    float* sb1 = (float*)(smc + SM_B1);
    float* sb2 = (float*)(smc + SM_B2);
    float* sdw = (float*)(smc + SM_DW);
    float* sred = (float*)(smc + SM_RED);

    const float* fin  = g_cur ? g_buf1 : g_buf0;
    float*       fout = g_cur ? g_buf0 : g_buf1;

    const int b  = blockIdx.z;
    const int y0 = blockIdx.y * TILE_H;
    const int x0 = blockIdx.x * TILE_W;
    const int tid = threadIdx.x;
    const int wwid = tid >> 5;
    const int lane = tid & 31;
    const int g2 = lane >> 2;
    const int t4 = lane & 3;

    // ---- stage weights / constants via cp.async ----
    {
        u32 sa1 = (u32)__cvta_generic_to_shared(sW1q);
        u32 sa2 = (u32)__cvta_generic_to_shared(sW2q);
        #pragma unroll
        for (int k = 0; k < 8; k++) {
            int i = tid + k * NT;                 // uint4 index 0..2047
            cp16(sa1 + i * 16, g_w1q + i * 4);
            cp16(sa2 + i * 16, g_w2q + i * 4);
        }
        if (tid < 144) cp16((u32)__cvta_generic_to_shared(sdw) + tid * 16, g_dws + tid * 4);
        else if (tid < 176) cp16((u32)__cvta_generic_to_shared(sb1) + (tid - 144) * 16, g_b1c + (tid - 144) * 4);
        else if (tid < 192) cp16((u32)__cvta_generic_to_shared(sb2) + (tid - 176) * 16, g_b2s + (tid - 176) * 4);
        asm volatile("cp.async.commit_group;" ::: "memory");
    }

    // ---- fp32 halo tile [64][10][18]; interior fast path ----
    {
        int c  = tid / 180;
        int rem = tid - c * 180;
        int rr = rem / 18;
        int xx = rem - rr * 18;
        int i = tid;
        const bool interior = (y0 != 0) && (y0 != H - TILE_H) && (x0 != 0) && (x0 != W - TILE_W);
        if (interior) {
            const float* gsrc = fin + ((b * C) * H + (y0 - 1)) * W + (x0 - 1);
            long goff = (long)c * HW + rr * W + xx;
            #pragma unroll 5
            for (int it = 0; it < 45; it++) {
                sf[i] = gsrc[goff];
                // advance logical (c,rr,xx) by (+1,+4,+4) with carries;
                // goff tracks c*HW + rr*W + xx exactly.
                i += 256; goff += HW + 4 * W + 4;
                rr += 4; xx += 4;
                if (xx >= 18) { xx -= 18; rr += 1; goff += W - 18; }
                if (rr >= 10) { rr -= 10; goff += HW - 10 * W; }
            }
        } else {
            #pragma unroll 5
            for (int it = 0; it < 45; it++) {
                int y = y0 - 1 + rr;
                int x = x0 - 1 + xx;
                float v = 0.0f;
                if ((unsigned)y < H && (unsigned)x < W)
                    v = fin[((b * C + c) * H + y) * W + x];
                sf[i] = v;
                i += 256; c += 1; rr += 4; xx += 4;
                if (xx >= 18) { xx -= 18; rr += 1; }
                if (rr >= 10) { rr -= 10; c += 1; }
            }
        }
    }
    asm volatile("cp.async.wait_group 0;" ::: "memory");
    __syncthreads();

    // ---- A1 fragments in registers straight from sf (truncation split) ----
    u32 ah[4][4], al[4][4];
    {
        const int pr = (wwid + 1) * 18 + 1;
        #pragma unroll
        for (int kc = 0; kc < 4; kc++) {
            #pragma unroll
            for (int q = 0; q < 2; q++) {
                int c = 16 * kc + 2 * t4 + 8 * q;
                float v00 = sf[c * 180 + pr + g2];
                float v01 = sf[(c + 1) * 180 + pr + g2];
                float v10 = sf[c * 180 + pr + g2 + 8];
                float v11 = sf[(c + 1) * 180 + pr + g2 + 8];
                ah[kc][2 * q]     = pack_trunc(v00, v01);
                ah[kc][2 * q + 1] = pack_trunc(v10, v11);
                al[kc][2 * q]     = pack_trunc(v00 - hi_trunc(v00), v01 - hi_trunc(v01));
                al[kc][2 * q + 1] = pack_trunc(v10 - hi_trunc(v10), v11 - hi_trunc(v11));
            }
        }
    }

    // ---- GEMM1 half -> gelu -> GEMM2 half, per hh ----
    float acc2[8][4];
    #pragma unroll
    for (int nt = 0; nt < 8; nt++)
        #pragma unroll
        for (int e = 0; e < 4; e++) acc2[nt][e] = 0.0f;

    #pragma unroll
    for (int hh = 0; hh < 2; hh++) {
        float acc[8][4];
        #pragma unroll
        for (int ntl = 0; ntl < 8; ntl++)
            #pragma unroll
            for (int e = 0; e < 4; e++) acc[ntl][e] = 0.0f;

        #pragma unroll
        for (int ntl = 0; ntl < 8; ntl++) {
            const int row = 8 * (8 * hh + ntl) + g2;
            const int rbase = row * 64;
            const int rsw = (row & 1) << 2;
            #pragma unroll
            for (int kc = 0; kc < 4; kc++) {
                int off = rbase + (((kc * 4 + t4) ^ rsw) << 2);
                uint4 wq = *(const uint4*)(sW1q + off);
                mma_bf16(acc[ntl], ah[kc], wq.x, wq.y);
                mma_bf16(acc[ntl], ah[kc], wq.z, wq.w);
                mma_bf16(acc[ntl], al[kc], wq.x, wq.y);
            }
        }

        u32 a2h[4][4], a2l[4][4];
        #pragma unroll
        for (int ntl = 0; ntl < 8; ntl++) {
            const int n = 8 * hh + ntl;
            float bias0 = sb1[8 * n + 2 * t4];
            float bias1 = sb1[8 * n + 2 * t4 + 1];
            float gl0 = gelu_f(acc[ntl][0] + bias0);
            float gl1 = gelu_f(acc[ntl][1] + bias1);
            float gl2 = gelu_f(acc[ntl][2] + bias0);
            float gl3 = gelu_f(acc[ntl][3] + bias1);
            int kcl = ntl >> 1;
            int q   = (ntl & 1) << 1;
            a2h[kcl][q]     = pack_trunc(gl0, gl1);
            a2h[kcl][q + 1] = pack_trunc(gl2, gl3);
            a2l[kcl][q]     = pack_trunc(gl0 - hi_trunc(gl0), gl1 - hi_trunc(gl1));
            a2l[kcl][q + 1] = pack_trunc(gl2 - hi_trunc(gl2), gl3 - hi_trunc(gl3));
        }

        #pragma unroll
        for (int nt = 0; nt < 8; nt++) {
            const int row = 8 * nt + g2;
            const int rbase = row * 128;
            const int rsw = (row & 1) << 2;
            #pragma unroll
            for (int kcl = 0; kcl < 4; kcl++) {
                int kc = 4 * hh + kcl;
                int off = rbase + (((kc * 4 + t4) ^ rsw) << 2);
                uint4 wq = *(const uint4*)(sW2q + off);
                mma_bf16(acc2[nt], a2h[kcl], wq.x, wq.y);
                mma_bf16(acc2[nt], a2h[kcl], wq.z, wq.w);
                mma_bf16(acc2[nt], a2l[kcl], wq.x, wq.y);
            }
        }
    }

    // ---- epilogue: depthwise (prescaled) + Euler + |delta| ----
    float lsum = 0.0f;
    #pragma unroll
    for (int nt = 0; nt < 8; nt++) {
        #pragma unroll
        for (int e = 0; e < 2; e++) {
            const int c = 8 * nt + 2 * t4 + e;
            const float* base = sf + c * 180;
            const float wd0 = sdw[c * 9 + 0], wd1 = sdw[c * 9 + 1], wd2 = sdw[c * 9 + 2];
            const float wd3 = sdw[c * 9 + 3], wd4 = sdw[c * 9 + 4], wd5 = sdw[c * 9 + 5];
            const float wd6 = sdw[c * 9 + 6], wd7 = sdw[c * 9 + 7], wd8 = sdw[c * 9 + 8];
            const float b2v = sb2[c];
            #pragma unroll
            for (int half = 0; half < 2; half++) {
                const int col = g2 + 8 * half;
                float s = b2v;
                s = fmaf(wd0, base[(wwid + 0) * 18 + col + 0], s);
                s = fmaf(wd1, base[(wwid + 0) * 18 + col + 1], s);
                s = fmaf(wd2, base[(wwid + 0) * 18 + col + 2], s);
                s = fmaf(wd3, base[(wwid + 1) * 18 + col + 0], s);
                s = fmaf(wd4, base[(wwid + 1) * 18 + col + 1], s);
                s = fmaf(wd5, base[(wwid + 1) * 18 + col + 2], s);
                s = fmaf(wd6, base[(wwid + 2) * 18 + col + 0], s);
                s = fmaf(wd7, base[(wwid + 2) * 18 + col + 1], s);
                s = fmaf(wd8, base[(wwid + 2) * 18 + col + 2], s);
                s = fmaf(DT_C, acc2[nt][2 * half + e], s);
                float fold = base[(wwid + 1) * 18 + col + 1];
                float fnew = fold + s;
                lsum += fabsf(s);
                fout[((b * C + c) * H + (y0 + wwid)) * W + (x0 + col)] = fnew;
            }
        }
    }

    // ---- reduce |delta|; last CTA finalizes the step ----
    #pragma unroll
    for (int off = 16; off > 0; off >>= 1)
        lsum += __shfl_xor_sync(0xFFFFFFFFu, lsum, off);
    if (lane == 0) sred[wwid] = lsum;
    __syncthreads();
    if (tid == 0) {
        float bs = 0.0f;
        #pragma unroll
        for (int i = 0; i < 8; i++) bs += sred[i];
        atomicAdd(&g_sum, (double)bs);
        __threadfence();
        unsigned prev = atomicAdd(&g_count, 1u);
        if (prev == NBLK - 1) {
            __threadfence();
            double mean = g_sum / (double)FIELD_N;
            g_steps += 1;
            if (mean < THRESH_C) g_done = 1;
            g_cur ^= 1;
            g_sum = 0.0;
            g_count = 0u;
            __threadfence();
        }
    }
}

__global__ void afe_output_kernel(float* __restrict__ out, int out_size) {
    const float* f = g_cur ? g_buf1 : g_buf0;
    int tid = blockIdx.x * blockDim.x + threadIdx.x;
    int stride = gridDim.x * blockDim.x;
    float stepsf = (float)g_steps;
    for (int i = tid; i < out_size; i += stride)
        out[i] = (i < FIELD_N) ? f[i] : stepsf;
}

extern "C" void kernel_launch(void* const* d_in, const int* in_sizes, int n_in,
                              void* d_out, int out_size) {
    const float* field  = (const float*)d_in[0];
    const float* dw     = (const float*)d_in[1];
    const float* db     = (const float*)d_in[2];
    const float* w1     = (const float*)d_in[3];
    const float* b1     = (const float*)d_in[4];
    const float* w2     = (const float*)d_in[5];
    const float* b2     = (const float*)d_in[6];
    const float* dcoeff = (const float*)d_in[7];

    cudaFuncSetAttribute(afe_step_kernel,
                         cudaFuncAttributeMaxDynamicSharedMemorySize, SMEM_BYTES);

    afe_init_kernel<<<1024, 256>>>(field);
    afe_prep_weights<<<64, 256>>>(w1, w2, dw, db, b1, b2, dcoeff);

    dim3 grid(W / TILE_W, H / TILE_H, BB);  // (8, 16, 4) = 512 CTAs
    for (int s = 0; s < MAX_STEPS; s++) {
        afe_step_kernel<<<grid, NT, SMEM_BYTES>>>();
    }

    afe_output_kernel<<<2048, 256>>>((float*)d_out, out_size);
}